// round 5
// baseline (speedup 1.0000x reference)
#include <cuda_runtime.h>

#define TLEN   2048
#define BATCH  8192
#define STEPS  8
#define NT     (TLEN / STEPS)   // 256 tiles
#define RING   6                // smem ring depth
#define BLOCKT 64               // 2 warps/block -> SMSP 0 and 1; 128 blocks, 1 per SM

__device__ __forceinline__ float frcp_fast(float x) {
    float r;
    asm("rcp.approx.f32 %0, %1;" : "=f"(r) : "f"(x));
    return r;
}

__device__ __forceinline__ void cpasync16(float4* dst, const float4* src) {
    unsigned d = (unsigned)__cvta_generic_to_shared(dst);
    asm volatile("cp.async.cg.shared.global [%0], [%1], 16;" :: "r"(d), "l"(src) : "memory");
}
__device__ __forceinline__ void cp_commit() {
    asm volatile("cp.async.commit_group;" ::: "memory");
}
__device__ __forceinline__ void cp_wait4() {
    asm volatile("cp.async.wait_group 4;" ::: "memory");
}

// per-tile precomputed transform (state-independent)
struct T8 {
    float a[STEPS], q[STEPS], r[STEPS], r2[STEPS], qs[STEPS], z[STEPS];
};

__shared__ float4 g_buf[RING][6][BLOCKT];   // 6*6*64*16 = 36 KB

__device__ __forceinline__ void issue_tile(int tile, int slot, int lane,
                                           const float4* p4, const float4* h4, const float4* s4)
{
    cpasync16(&g_buf[slot][0][lane], p4 + 2 * tile + 0);
    cpasync16(&g_buf[slot][1][lane], p4 + 2 * tile + 1);
    cpasync16(&g_buf[slot][2][lane], h4 + 2 * tile + 0);
    cpasync16(&g_buf[slot][3][lane], h4 + 2 * tile + 1);
    cpasync16(&g_buf[slot][4][lane], s4 + 2 * tile + 0);
    cpasync16(&g_buf[slot][5][lane], s4 + 2 * tile + 1);
    cp_commit();
}

// read smem slot, compute transform arrays (all off the carried chain)
__device__ __forceinline__ void xform(int slot, int lane, T8& o)
{
    const float4 pv0 = g_buf[slot][0][lane];
    const float4 pv1 = g_buf[slot][1][lane];
    const float4 hv0 = g_buf[slot][2][lane];
    const float4 hv1 = g_buf[slot][3][lane];
    const float4 sv0 = g_buf[slot][4][lane];
    const float4 sv1 = g_buf[slot][5][lane];

    const float zz[8] = {pv0.x, pv0.y, pv0.z, pv0.w, pv1.x, pv1.y, pv1.z, pv1.w};
    const float hh[8] = {hv0.x, hv0.y, hv0.z, hv0.w, hv1.x, hv1.y, hv1.z, hv1.w};
    const float ss[8] = {sv0.x, sv0.y, sv0.z, sv0.w, sv1.x, sv1.y, sv1.z, sv1.w};

    #pragma unroll
    for (int j = 0; j < STEPS; j++) {
        const float e = __expf(5.0f - 10.0f * hh[j]);          // EX2 (MUFU)
        const float a = fmaf(0.5f, frcp_fast(1.0f + e), 0.5f); // sigmoid (MUFU)
        const float r = fmaxf(100.0f * ss[j], 1.0f);
        const float q = 0.1f * r;
        o.a[j]  = a;
        o.q[j]  = q;
        o.r[j]  = r;
        o.r2[j] = r * r;
        o.qs[j] = q + r;
        o.z[j]  = zz[j];
    }
}

// 8 EKF steps; carried chain: S@12 -> rcp@28 -> {p00,p01,p11}@32
__device__ __forceinline__ void chain8(const T8& C,
                                       float& p00, float& p01, float& p11,
                                       float& x0, float& x1,
                                       float4* o4)
{
    float ox[16];
    #pragma unroll
    for (int j = 0; j < STEPS; j++) {
        const float a  = C.a[j];
        const float p01n = fmaf(a, p11, p01);
        const float X    = fmaf(a, p01, p00 + C.qs[j]);
        const float S    = fmaf(a, p01n, X);           // = P_pred00 + scale
        const float Sinv = frcp_fast(S);               // 1e-6 negligible (S >= 1)

        // off-chain products, computed in the rcp shadow
        const float rm   = p01n * C.r[j];
        const float n2   = p01n * p01n;
        const float p11n = p11 + C.q[j];
        const float xp0  = fmaf(a, x1, x0);
        const float y    = C.z[j] - xp0;

        const float K0 = fmaf(-C.r[j], Sinv, 1.0f);    // 1 - r/S
        const float K1 = p01n * Sinv;

        p00 = fmaf(-C.r2[j], Sinv, C.r[j]);            // r - r^2/S
        p01 = rm * Sinv;                               // r*p01n/S
        p11 = fmaf(-n2, Sinv, p11n);                   // p11n - p01n^2/S
        x0  = fmaf(K0, y, xp0);
        x1  = fmaf(K1, y, x1);

        ox[2 * j + 0] = x0;
        ox[2 * j + 1] = x1;
    }
    #pragma unroll
    for (int i = 0; i < 4; i++) {
        float4 o;
        o.x = ox[4 * i + 0];
        o.y = ox[4 * i + 1];
        o.z = ox[4 * i + 2];
        o.w = ox[4 * i + 3];
        o4[i] = o;
    }
}

__global__ void __launch_bounds__(BLOCKT)
ekf_kernel(const float* __restrict__ price,
           const float* __restrict__ hurst,
           const float* __restrict__ sigv,
           float* __restrict__ out)
{
    const int lane = threadIdx.x;                 // 0..63 (smem index)
    const int b = blockIdx.x * BLOCKT + lane;     // grid = BATCH/BLOCKT

    const float4* __restrict__ p4 = (const float4*)(price + (size_t)b * TLEN);
    const float4* __restrict__ h4 = (const float4*)(hurst + (size_t)b * TLEN);
    const float4* __restrict__ s4 = (const float4*)(sigv  + (size_t)b * TLEN);
    float4* __restrict__ o4 = (float4*)(out + (size_t)b * TLEN * 2);

    // prologue: issue tiles 0..4 (5 groups), wait so tile 0 is resident
    #pragma unroll
    for (int t = 0; t < RING - 1; t++)
        issue_tile(t, t, lane, p4, h4, s4);
    cp_wait4();

    T8 A, B;
    xform(0, lane, A);

    // initial state from tile 0 (dt = 1)
    float x0 = A.z[0];
    float x1 = A.z[1] - A.z[0];
    float p00 = 1.0f, p01 = 0.0f, p11 = 1.0f;

    // ping-pong over tile pairs; NT = 256 (even)
    #pragma unroll 1
    for (int t = 0; t < NT; t += 2) {
        // ---- body A: chain on A, prefetch+transform t+1 into B ----
        {
            const int it = t + RING - 1;
            issue_tile((it < NT) ? it : (NT - 1), it % RING, lane, p4, h4, s4);
            cp_wait4();                        // tile t+1 resident
            xform((t + 1) % RING, lane, B);    // fills A-chain stall slots
            chain8(A, p00, p01, p11, x0, x1, o4 + 4 * t);
        }
        // ---- body B: chain on B, prefetch+transform t+2 into A ----
        {
            const int it = t + RING;
            issue_tile((it < NT) ? it : (NT - 1), it % RING, lane, p4, h4, s4);
            cp_wait4();                        // tile t+2 resident
            const int xt = (t + 2 < NT) ? (t + 2) : (NT - 1);
            xform(xt % RING, lane, A);
            chain8(B, p00, p01, p11, x0, x1, o4 + 4 * (t + 1));
        }
    }
}

extern "C" void kernel_launch(void* const* d_in, const int* in_sizes, int n_in,
                              void* d_out, int out_size)
{
    const float* price = (const float*)d_in[0];
    const float* hurst = (const float*)d_in[1];
    const float* sigv  = (const float*)d_in[2];
    float* out = (float*)d_out;

    // 128 blocks x 64 threads: 1 block/SM on 128 SMs, warps on SMSP 0 and 1
    // -> every warp owns a private scheduler (no SMSP sharing)
    ekf_kernel<<<BATCH / BLOCKT, BLOCKT>>>(price, hurst, sigv, out);
}

// round 6
// speedup vs baseline: 1.0169x; 1.0169x over previous
#include <cuda_runtime.h>

#define TLEN   2048
#define BATCH  8192
#define STEPS  8
#define NT     (TLEN / STEPS)   // 256 tiles
#define RING   6                // smem ring depth
#define BLOCKT 64

__device__ __forceinline__ float frcp_fast(float x) {
    float r;
    asm("rcp.approx.f32 %0, %1;" : "=f"(r) : "f"(x));
    return r;
}
__device__ __forceinline__ float ftanh_fast(float x) {
    float r;
    asm("tanh.approx.f32 %0, %1;" : "=f"(r) : "f"(x));
    return r;
}

__device__ __forceinline__ void cpasync16(float4* dst, const float4* src) {
    unsigned d = (unsigned)__cvta_generic_to_shared(dst);
    asm volatile("cp.async.cg.shared.global [%0], [%1], 16;" :: "r"(d), "l"(src) : "memory");
}
__device__ __forceinline__ void cp_commit() {
    asm volatile("cp.async.commit_group;" ::: "memory");
}
__device__ __forceinline__ void cp_wait4() {
    asm volatile("cp.async.wait_group 4;" ::: "memory");
}

__shared__ float4 g_buf[RING][6][BLOCKT];   // 36 KB

__device__ __forceinline__ void issue_tile(int tile, int slot, int lane,
                                           const float4* p4, const float4* h4, const float4* s4)
{
    cpasync16(&g_buf[slot][0][lane], p4 + 2 * tile + 0);
    cpasync16(&g_buf[slot][1][lane], p4 + 2 * tile + 1);
    cpasync16(&g_buf[slot][2][lane], h4 + 2 * tile + 0);
    cpasync16(&g_buf[slot][3][lane], h4 + 2 * tile + 1);
    cpasync16(&g_buf[slot][4][lane], s4 + 2 * tile + 0);
    cpasync16(&g_buf[slot][5][lane], s4 + 2 * tile + 1);
    cp_commit();
}

// 8 EKF steps with INLINE per-step transform (no precomputed arrays -> no spills).
// Carried chain: S@12 -> rcp@28 -> {p00,p01,p11}@32. Transform ops are
// state-independent and get hoisted into chain bubbles by ptxas.
__device__ __forceinline__ void tile8(const float4& pv0, const float4& pv1,
                                      const float4& hv0, const float4& hv1,
                                      const float4& sv0, const float4& sv1,
                                      float& p00, float& p01, float& p11,
                                      float& x0, float& x1,
                                      float4* o4)
{
    const float zz[8] = {pv0.x, pv0.y, pv0.z, pv0.w, pv1.x, pv1.y, pv1.z, pv1.w};
    const float hh[8] = {hv0.x, hv0.y, hv0.z, hv0.w, hv1.x, hv1.y, hv1.z, hv1.w};
    const float ss[8] = {sv0.x, sv0.y, sv0.z, sv0.w, sv1.x, sv1.y, sv1.z, sv1.w};

    float4 o;
    #pragma unroll
    for (int j = 0; j < STEPS; j++) {
        // ---- transform (off the carried chain) ----
        // rho = 0.5 + 0.5*sigmoid(10(h-0.5)) = 0.75 + 0.25*tanh(5h - 2.5); a = dt*rho
        const float a  = fmaf(0.25f, ftanh_fast(fmaf(5.0f, hh[j], -2.5f)), 0.75f);
        const float r  = fmaxf(100.0f * ss[j], 1.0f);   // scale
        const float q  = 0.1f * r;
        const float qs = 1.1f * r;                       // q + scale, exact
        const float r2 = r * r;

        // ---- carried chain ----
        const float p01n = fmaf(a, p11, p01);
        const float X    = fmaf(a, p01, p00 + qs);
        const float S    = fmaf(a, p01n, X);             // P_pred00 + scale
        const float Sinv = frcp_fast(S);                 // S >= 1

        // rcp-shadow work
        const float rm   = p01n * r;
        const float n2   = p01n * p01n;
        const float p11n = p11 + q;
        const float xp0  = fmaf(a, x1, x0);
        const float y    = zz[j] - xp0;

        const float K0 = fmaf(-r, Sinv, 1.0f);           // 1 - r/S
        const float K1 = p01n * Sinv;

        p00 = fmaf(-r2, Sinv, r);                        // r - r^2/S
        p01 = rm * Sinv;
        p11 = fmaf(-n2, Sinv, p11n);
        x0  = fmaf(K0, y, xp0);
        x1  = fmaf(K1, y, x1);

        // pack outputs straight into a float4; STG.128 every 2 steps
        if ((j & 1) == 0) { o.x = x0; o.y = x1; }
        else              { o.z = x0; o.w = x1; o4[j >> 1] = o; }
    }
}

__global__ void __launch_bounds__(BLOCKT)
ekf_kernel(const float* __restrict__ price,
           const float* __restrict__ hurst,
           const float* __restrict__ sigv,
           float* __restrict__ out)
{
    const int lane = threadIdx.x;
    const int b = blockIdx.x * BLOCKT + lane;

    const float4* __restrict__ p4 = (const float4*)(price + (size_t)b * TLEN);
    const float4* __restrict__ h4 = (const float4*)(hurst + (size_t)b * TLEN);
    const float4* __restrict__ s4 = (const float4*)(sigv  + (size_t)b * TLEN);
    float4* __restrict__ o4 = (float4*)(out + (size_t)b * TLEN * 2);

    // prologue: issue tiles 0..4, wait so tile 0 resident
    #pragma unroll
    for (int t = 0; t < RING - 1; t++)
        issue_tile(t, t, lane, p4, h4, s4);
    cp_wait4();

    // tile 0 -> register set A
    float4 pA0 = g_buf[0][0][lane], pA1 = g_buf[0][1][lane];
    float4 hA0 = g_buf[0][2][lane], hA1 = g_buf[0][3][lane];
    float4 sA0 = g_buf[0][4][lane], sA1 = g_buf[0][5][lane];

    // initial state (dt = 1)
    float x0 = pA0.x;
    float x1 = pA0.y - pA0.x;
    float p00 = 1.0f, p01 = 0.0f, p11 = 1.0f;

    float4 pB0, pB1, hB0, hB1, sB0, sB1;

    // ping-pong over tile pairs; NT = 256 (even)
    #pragma unroll 1
    for (int t = 0; t < NT; t += 2) {
        // ---- body A: prefetch t+1 -> B, process tile t from A ----
        {
            const int it = t + RING - 1;
            issue_tile((it < NT) ? it : (NT - 1), it % RING, lane, p4, h4, s4);
            cp_wait4();                                  // tile t+1 resident
            const int sl = (t + 1) % RING;
            pB0 = g_buf[sl][0][lane]; pB1 = g_buf[sl][1][lane];
            hB0 = g_buf[sl][2][lane]; hB1 = g_buf[sl][3][lane];
            sB0 = g_buf[sl][4][lane]; sB1 = g_buf[sl][5][lane];
            tile8(pA0, pA1, hA0, hA1, sA0, sA1, p00, p01, p11, x0, x1, o4 + 4 * t);
        }
        // ---- body B: prefetch t+2 -> A, process tile t+1 from B ----
        {
            const int it = t + RING;
            issue_tile((it < NT) ? it : (NT - 1), it % RING, lane, p4, h4, s4);
            cp_wait4();                                  // tile t+2 resident
            const int tn = (t + 2 < NT) ? (t + 2) : (NT - 1);
            const int sl = tn % RING;
            pA0 = g_buf[sl][0][lane]; pA1 = g_buf[sl][1][lane];
            hA0 = g_buf[sl][2][lane]; hA1 = g_buf[sl][3][lane];
            sA0 = g_buf[sl][4][lane]; sA1 = g_buf[sl][5][lane];
            tile8(pB0, pB1, hB0, hB1, sB0, sB1, p00, p01, p11, x0, x1, o4 + 4 * (t + 1));
        }
    }
}

extern "C" void kernel_launch(void* const* d_in, const int* in_sizes, int n_in,
                              void* d_out, int out_size)
{
    const float* price = (const float*)d_in[0];
    const float* hurst = (const float*)d_in[1];
    const float* sigv  = (const float*)d_in[2];
    float* out = (float*)d_out;

    ekf_kernel<<<BATCH / BLOCKT, BLOCKT>>>(price, hurst, sigv, out);
}